// round 3
// baseline (speedup 1.0000x reference)
#include <cuda_runtime.h>
#include <cstdint>

#define D 128
#define MAX_NODES 100000

// 51.2 MB device scratch for h = node_emb @ W^T.
// float4 type guarantees 16B alignment for vector ld/st.
__device__ float4 g_h4[(size_t)MAX_NODES * (D / 4)];

// ---------------------------------------------------------------------------
// Kernel 1: h = x @ W^T   (x: [N,128] row-major, W: [128,128] row-major)
// h[m][n] = sum_k x[m][k] * W[n][k]
// Block = 128 rows x 128 cols, 256 threads, 8x8 register tile per thread.
// ---------------------------------------------------------------------------
__global__ __launch_bounds__(256) void gemm_kernel(const float* __restrict__ x,
                                                   const float* __restrict__ W,
                                                   int n_rows) {
    __shared__ float xs[8][132];  // xs[k][m]
    __shared__ float ws[8][132];  // ws[k][n] = W[n][k0+k]

    const int tid = threadIdx.x;
    const int block_row = blockIdx.x * 128;
    const int ty = tid >> 4;          // 0..15: row group (8 rows each)
    const int tx = tid & 15;          // 0..15: col group (8 cols each)
    const int r_load = tid >> 1;      // 0..127
    const int k_half = (tid & 1) * 4; // 0 or 4

    float acc[8][8];
#pragma unroll
    for (int i = 0; i < 8; i++)
#pragma unroll
        for (int j = 0; j < 8; j++) acc[i][j] = 0.f;

    for (int k0 = 0; k0 < D; k0 += 8) {
        {
            const int gr = block_row + r_load;
            float4 v = make_float4(0.f, 0.f, 0.f, 0.f);
            if (gr < n_rows)
                v = *(const float4*)(x + (size_t)gr * D + k0 + k_half);
            xs[k_half + 0][r_load] = v.x;
            xs[k_half + 1][r_load] = v.y;
            xs[k_half + 2][r_load] = v.z;
            xs[k_half + 3][r_load] = v.w;
        }
        {
            const float4 v = *(const float4*)(W + (size_t)r_load * D + k0 + k_half);
            ws[k_half + 0][r_load] = v.x;
            ws[k_half + 1][r_load] = v.y;
            ws[k_half + 2][r_load] = v.z;
            ws[k_half + 3][r_load] = v.w;
        }
        __syncthreads();

#pragma unroll
        for (int kk = 0; kk < 8; kk++) {
            float a[8], b[8];
            *(float4*)&a[0] = *(const float4*)&xs[kk][ty * 8];
            *(float4*)&a[4] = *(const float4*)&xs[kk][ty * 8 + 4];
            *(float4*)&b[0] = *(const float4*)&ws[kk][tx * 8];
            *(float4*)&b[4] = *(const float4*)&ws[kk][tx * 8 + 4];
#pragma unroll
            for (int i = 0; i < 8; i++)
#pragma unroll
                for (int j = 0; j < 8; j++)
                    acc[i][j] += a[i] * b[j];
        }
        __syncthreads();
    }

#pragma unroll
    for (int i = 0; i < 8; i++) {
        const int gr = block_row + ty * 8 + i;
        if (gr < n_rows) {
            float4* dst = &g_h4[(size_t)gr * (D / 4) + tx * 2];
            dst[0] = make_float4(acc[i][0], acc[i][1], acc[i][2], acc[i][3]);
            dst[1] = make_float4(acc[i][4], acc[i][5], acc[i][6], acc[i][7]);
        }
    }
}

// ---------------------------------------------------------------------------
// Kernel 2: scatter  out[row[e]] += w[e] * h[col[e]]
// edges are INT32 (JAX x64-disabled downgrades int64 -> int32).
// One warp per edge; lane l owns float4 at element offset 4l.
// Coalesced 512B gather per warp; red.global.add.v4.f32 reduction (no read-back).
// ---------------------------------------------------------------------------
__global__ __launch_bounds__(256) void scatter_kernel(const int* __restrict__ edges,
                                                      const float* __restrict__ w,
                                                      float* __restrict__ out,
                                                      int n_edges, int n_nodes) {
    const int lane = threadIdx.x & 31;
    const int warp = (blockIdx.x * blockDim.x + threadIdx.x) >> 5;
    const int n_warps = (gridDim.x * blockDim.x) >> 5;

    for (int e = warp; e < n_edges; e += n_warps) {
        const int row = edges[e];
        const int col = edges[n_edges + e];
        const float wt = w[e];

        // Defensive guard: if layout assumptions are wrong we want rel_err
        // signal, not a crash.
        if ((unsigned)row >= (unsigned)n_nodes || (unsigned)col >= (unsigned)n_nodes)
            continue;

        const float4 v = g_h4[(size_t)col * (D / 4) + lane];
        const float4 m = make_float4(v.x * wt, v.y * wt, v.z * wt, v.w * wt);

        float* dst = out + (size_t)row * D + lane * 4;
        asm volatile("red.global.add.v4.f32 [%0], {%1, %2, %3, %4};"
                     :: "l"(dst), "f"(m.x), "f"(m.y), "f"(m.z), "f"(m.w)
                     : "memory");
    }
}

// ---------------------------------------------------------------------------
// Launch
// ---------------------------------------------------------------------------
extern "C" void kernel_launch(void* const* d_in, const int* in_sizes, int n_in,
                              void* d_out, int out_size) {
    const float* node_emb    = (const float*)d_in[0];
    const int*   edges       = (const int*)d_in[1];
    const float* edge_weight = (const float*)d_in[2];
    const float* W           = (const float*)d_in[3];
    float*       out         = (float*)d_out;

    const int n_nodes = in_sizes[0] / D;
    const int n_edges = in_sizes[1] / 2;

    // zero the output (poisoned by harness)
    cudaMemsetAsync(d_out, 0, (size_t)out_size * sizeof(float), 0);

    // GEMM: h = node_emb @ W^T  (writes g_h4)
    const int gemm_blocks = (n_nodes + 127) / 128;
    gemm_kernel<<<gemm_blocks, 256, 0, 0>>>(node_emb, W, n_nodes);

    // Scatter with vectorized global reductions
    scatter_kernel<<<2048, 256, 0, 0>>>(edges, edge_weight, out, n_edges, n_nodes);
}

// round 4
// speedup vs baseline: 1.0889x; 1.0889x over previous
#include <cuda_runtime.h>
#include <cstdint>

#define D 128
#define MAX_NODES 100032
#define MAX_EDGES 3200000

// ---- device scratch (static globals; allocation-free) ----
__device__ float4 g_h4[(size_t)MAX_NODES * (D / 4)];          // 51.2 MB  h = x@W^T
__device__ int2   g_csr[MAX_EDGES];                            // 25.6 MB  (col, w-bits)
__device__ int    g_count[MAX_NODES];                          // per-row degree
__device__ int    g_start[MAX_NODES + 1];                      // CSR row starts
__device__ int    g_cursor[MAX_NODES];                         // fill cursors

// ---------------------------------------------------------------------------
// Kernel 1: h = x @ W^T  (fp32 register-tiled SGEMM, 128x128 block, 8x8/thread)
// ---------------------------------------------------------------------------
__global__ __launch_bounds__(256) void gemm_kernel(const float* __restrict__ x,
                                                   const float* __restrict__ W,
                                                   int n_rows) {
    __shared__ float xs[8][132];
    __shared__ float ws[8][132];

    const int tid = threadIdx.x;
    const int block_row = blockIdx.x * 128;
    const int ty = tid >> 4;
    const int tx = tid & 15;
    const int r_load = tid >> 1;
    const int k_half = (tid & 1) * 4;

    float acc[8][8];
#pragma unroll
    for (int i = 0; i < 8; i++)
#pragma unroll
        for (int j = 0; j < 8; j++) acc[i][j] = 0.f;

    for (int k0 = 0; k0 < D; k0 += 8) {
        {
            const int gr = block_row + r_load;
            float4 v = make_float4(0.f, 0.f, 0.f, 0.f);
            if (gr < n_rows)
                v = *(const float4*)(x + (size_t)gr * D + k0 + k_half);
            xs[k_half + 0][r_load] = v.x;
            xs[k_half + 1][r_load] = v.y;
            xs[k_half + 2][r_load] = v.z;
            xs[k_half + 3][r_load] = v.w;
        }
        {
            const float4 v = *(const float4*)(W + (size_t)r_load * D + k0 + k_half);
            ws[k_half + 0][r_load] = v.x;
            ws[k_half + 1][r_load] = v.y;
            ws[k_half + 2][r_load] = v.z;
            ws[k_half + 3][r_load] = v.w;
        }
        __syncthreads();

#pragma unroll
        for (int kk = 0; kk < 8; kk++) {
            float a[8], b[8];
            *(float4*)&a[0] = *(const float4*)&xs[kk][ty * 8];
            *(float4*)&a[4] = *(const float4*)&xs[kk][ty * 8 + 4];
            *(float4*)&b[0] = *(const float4*)&ws[kk][tx * 8];
            *(float4*)&b[4] = *(const float4*)&ws[kk][tx * 8 + 4];
#pragma unroll
            for (int i = 0; i < 8; i++)
#pragma unroll
                for (int j = 0; j < 8; j++)
                    acc[i][j] += a[i] * b[j];
        }
        __syncthreads();
    }

#pragma unroll
    for (int i = 0; i < 8; i++) {
        const int gr = block_row + ty * 8 + i;
        if (gr < n_rows) {
            float4* dst = &g_h4[(size_t)gr * (D / 4) + tx * 2];
            dst[0] = make_float4(acc[i][0], acc[i][1], acc[i][2], acc[i][3]);
            dst[1] = make_float4(acc[i][4], acc[i][5], acc[i][6], acc[i][7]);
        }
    }
}

// ---------------------------------------------------------------------------
// CSR build
// ---------------------------------------------------------------------------
__global__ void zero_count_kernel(int n_nodes) {
    int i = blockIdx.x * blockDim.x + threadIdx.x;
    if (i < n_nodes) g_count[i] = 0;
}

__global__ void hist_kernel(const int* __restrict__ edges, int n_edges, int n_nodes) {
    int e = blockIdx.x * blockDim.x + threadIdx.x;
    if (e < n_edges) {
        int row = edges[e];
        if ((unsigned)row < (unsigned)n_nodes)
            atomicAdd(&g_count[row], 1);
    }
}

// Single-block exclusive scan: 1024 threads, each owns a contiguous chunk.
__global__ __launch_bounds__(1024) void scan_kernel(int n_nodes, int n_edges) {
    const int T = 1024;
    const int tid = threadIdx.x;
    const int per = (n_nodes + T - 1) / T;
    const int lo = tid * per;
    const int hi = min(lo + per, n_nodes);

    int sum = 0;
    for (int i = lo; i < hi; i++) sum += g_count[i];

    __shared__ int s[1024];
    s[tid] = sum;
    __syncthreads();
#pragma unroll
    for (int off = 1; off < 1024; off <<= 1) {
        int v = (tid >= off) ? s[tid - off] : 0;
        __syncthreads();
        s[tid] += v;
        __syncthreads();
    }
    int run = s[tid] - sum;  // exclusive prefix of this chunk

    for (int i = lo; i < hi; i++) {
        int c = g_count[i];
        g_start[i] = run;
        g_cursor[i] = run;
        run += c;
    }
    if (tid == T - 1) g_start[n_nodes] = n_edges;
}

__global__ void fill_kernel(const int* __restrict__ edges,
                            const float* __restrict__ w,
                            int n_edges, int n_nodes) {
    int e = blockIdx.x * blockDim.x + threadIdx.x;
    if (e < n_edges) {
        int row = edges[e];
        int col = edges[n_edges + e];
        if ((unsigned)row >= (unsigned)n_nodes || (unsigned)col >= (unsigned)n_nodes)
            return;
        int pos = atomicAdd(&g_cursor[row], 1);
        g_csr[pos] = make_int2(col, __float_as_int(w[e]));
    }
}

// ---------------------------------------------------------------------------
// Aggregation: one warp per output node, no atomics.
// out[node] = sum_{e in row(node)} w[e] * h[col[e]]
// ---------------------------------------------------------------------------
__global__ __launch_bounds__(256) void agg_kernel(float* __restrict__ out, int n_nodes) {
    const int lane = threadIdx.x & 31;
    const int node = (blockIdx.x * blockDim.x + threadIdx.x) >> 5;
    if (node >= n_nodes) return;

    const int s = g_start[node];
    const int e = g_start[node + 1];

    float4 acc = make_float4(0.f, 0.f, 0.f, 0.f);
#pragma unroll 4
    for (int i = s; i < e; i++) {
        const int2 cw = g_csr[i];                 // warp-uniform broadcast
        const float wt = __int_as_float(cw.y);
        const float4 v = g_h4[(size_t)cw.x * (D / 4) + lane];
        acc.x += wt * v.x;
        acc.y += wt * v.y;
        acc.z += wt * v.z;
        acc.w += wt * v.w;
    }
    ((float4*)(out + (size_t)node * D))[lane] = acc;
}

// ---------------------------------------------------------------------------
// Launch
// ---------------------------------------------------------------------------
extern "C" void kernel_launch(void* const* d_in, const int* in_sizes, int n_in,
                              void* d_out, int out_size) {
    const float* node_emb    = (const float*)d_in[0];
    const int*   edges       = (const int*)d_in[1];
    const float* edge_weight = (const float*)d_in[2];
    const float* W           = (const float*)d_in[3];
    float*       out         = (float*)d_out;

    const int n_nodes = in_sizes[0] / D;
    const int n_edges = in_sizes[1] / 2;

    // GEMM: h = node_emb @ W^T
    gemm_kernel<<<(n_nodes + 127) / 128, 256, 0, 0>>>(node_emb, W, n_nodes);

    // CSR build (row-grouped edge list; no ordering needed within a row)
    zero_count_kernel<<<(n_nodes + 255) / 256, 256, 0, 0>>>(n_nodes);
    hist_kernel<<<(n_edges + 255) / 256, 256, 0, 0>>>(edges, n_edges, n_nodes);
    scan_kernel<<<1, 1024, 0, 0>>>(n_nodes, n_edges);
    fill_kernel<<<(n_edges + 255) / 256, 256, 0, 0>>>(edges, edge_weight, n_edges, n_nodes);

    // Atomic-free aggregation; writes every output row (covers zero-degree nodes)
    const int agg_threads = n_nodes * 32;
    agg_kernel<<<(agg_threads + 255) / 256, 256, 0, 0>>>(out, n_nodes);
}

// round 5
// speedup vs baseline: 1.6969x; 1.5584x over previous
#include <cuda_runtime.h>
#include <cstdint>

#define D 128
#define MAX_NODES 100032
#define MAX_EDGES 3200000
#define CHUNK 1024
#define MAX_CHUNKS 1024

// ---- device scratch (static globals; allocation-free) ----
__device__ float4 g_h4[(size_t)MAX_NODES * (D / 4)];   // 51.2 MB  h = x@W^T
__device__ int2   g_csr[MAX_EDGES];                    // 25.6 MB  (col, w-bits)
__device__ int    g_count[MAX_NODES];                  // per-row degree
__device__ int    g_start[MAX_NODES + 1];              // CSR row starts
__device__ int    g_cursor[MAX_NODES];                 // fill cursors
__device__ int    g_chunk_sum[MAX_CHUNKS];             // per-chunk degree sums
__device__ int    g_chunk_off[MAX_CHUNKS];             // exclusive chunk offsets

// ---------------------------------------------------------------------------
// Kernel 1: h = x @ W^T  (fp32 register-tiled SGEMM, 128x128 block, 8x8/thread)
// ---------------------------------------------------------------------------
__global__ __launch_bounds__(256) void gemm_kernel(const float* __restrict__ x,
                                                   const float* __restrict__ W,
                                                   int n_rows) {
    __shared__ float xs[8][132];
    __shared__ float ws[8][132];

    const int tid = threadIdx.x;
    const int block_row = blockIdx.x * 128;
    const int ty = tid >> 4;
    const int tx = tid & 15;
    const int r_load = tid >> 1;
    const int k_half = (tid & 1) * 4;

    float acc[8][8];
#pragma unroll
    for (int i = 0; i < 8; i++)
#pragma unroll
        for (int j = 0; j < 8; j++) acc[i][j] = 0.f;

    for (int k0 = 0; k0 < D; k0 += 8) {
        {
            const int gr = block_row + r_load;
            float4 v = make_float4(0.f, 0.f, 0.f, 0.f);
            if (gr < n_rows)
                v = *(const float4*)(x + (size_t)gr * D + k0 + k_half);
            xs[k_half + 0][r_load] = v.x;
            xs[k_half + 1][r_load] = v.y;
            xs[k_half + 2][r_load] = v.z;
            xs[k_half + 3][r_load] = v.w;
        }
        {
            const float4 v = *(const float4*)(W + (size_t)r_load * D + k0 + k_half);
            ws[k_half + 0][r_load] = v.x;
            ws[k_half + 1][r_load] = v.y;
            ws[k_half + 2][r_load] = v.z;
            ws[k_half + 3][r_load] = v.w;
        }
        __syncthreads();

#pragma unroll
        for (int kk = 0; kk < 8; kk++) {
            float a[8], b[8];
            *(float4*)&a[0] = *(const float4*)&xs[kk][ty * 8];
            *(float4*)&a[4] = *(const float4*)&xs[kk][ty * 8 + 4];
            *(float4*)&b[0] = *(const float4*)&ws[kk][tx * 8];
            *(float4*)&b[4] = *(const float4*)&ws[kk][tx * 8 + 4];
#pragma unroll
            for (int i = 0; i < 8; i++)
#pragma unroll
                for (int j = 0; j < 8; j++)
                    acc[i][j] += a[i] * b[j];
        }
        __syncthreads();
    }

#pragma unroll
    for (int i = 0; i < 8; i++) {
        const int gr = block_row + ty * 8 + i;
        if (gr < n_rows) {
            float4* dst = &g_h4[(size_t)gr * (D / 4) + tx * 2];
            dst[0] = make_float4(acc[i][0], acc[i][1], acc[i][2], acc[i][3]);
            dst[1] = make_float4(acc[i][4], acc[i][5], acc[i][6], acc[i][7]);
        }
    }
}

// ---------------------------------------------------------------------------
// CSR build
// ---------------------------------------------------------------------------
__global__ void zero_count_kernel(int n_nodes) {
    int i = blockIdx.x * blockDim.x + threadIdx.x;
    if (i < n_nodes) g_count[i] = 0;
}

__global__ void hist_kernel(const int* __restrict__ edges, int n_edges, int n_nodes) {
    int e = blockIdx.x * blockDim.x + threadIdx.x;
    if (e < n_edges) {
        int row = edges[e];
        if ((unsigned)row < (unsigned)n_nodes)
            atomicAdd(&g_count[row], 1);
    }
}

// Level 1: per-chunk reduce. One block of 256 threads sums CHUNK counters.
__global__ __launch_bounds__(256) void chunk_reduce_kernel(int n_nodes) {
    const int base = blockIdx.x * CHUNK;
    const int tid = threadIdx.x;

    int sum = 0;
#pragma unroll
    for (int j = 0; j < CHUNK / 256; j++) {
        int i = base + j * 256 + tid;
        if (i < n_nodes) sum += g_count[i];
    }
    // warp + block reduce
    for (int off = 16; off > 0; off >>= 1)
        sum += __shfl_down_sync(0xffffffffu, sum, off);
    __shared__ int ws[8];
    if ((tid & 31) == 0) ws[tid >> 5] = sum;
    __syncthreads();
    if (tid < 8) {
        int v = ws[tid];
        for (int off = 4; off > 0; off >>= 1)
            v += __shfl_down_sync(0xffu, v, off);
        if (tid == 0) g_chunk_sum[blockIdx.x] = v;
    }
}

// Level 2: single-block exclusive scan of chunk sums (n_chunks <= 1024).
__global__ __launch_bounds__(1024) void chunk_scan_kernel(int n_chunks, int n_nodes,
                                                          int n_edges) {
    const int tid = threadIdx.x;
    __shared__ int s[MAX_CHUNKS];
    int v = (tid < n_chunks) ? g_chunk_sum[tid] : 0;
    s[tid] = v;
    __syncthreads();
#pragma unroll
    for (int off = 1; off < MAX_CHUNKS; off <<= 1) {
        int t = (tid >= off) ? s[tid - off] : 0;
        __syncthreads();
        s[tid] += t;
        __syncthreads();
    }
    if (tid < n_chunks) g_chunk_off[tid] = s[tid] - v;  // exclusive
    if (tid == 0) g_start[n_nodes] = n_edges;
}

// Level 3: per-chunk exclusive scan + offset -> g_start / g_cursor.
__global__ __launch_bounds__(1024) void chunk_apply_kernel(int n_nodes) {
    const int tid = threadIdx.x;
    const int i = blockIdx.x * CHUNK + tid;

    __shared__ int s[CHUNK];
    int v = (i < n_nodes) ? g_count[i] : 0;
    s[tid] = v;
    __syncthreads();
#pragma unroll
    for (int off = 1; off < CHUNK; off <<= 1) {
        int t = (tid >= off) ? s[tid - off] : 0;
        __syncthreads();
        s[tid] += t;
        __syncthreads();
    }
    if (i < n_nodes) {
        int start = g_chunk_off[blockIdx.x] + s[tid] - v;
        g_start[i] = start;
        g_cursor[i] = start;
    }
}

__global__ void fill_kernel(const int* __restrict__ edges,
                            const float* __restrict__ w,
                            int n_edges, int n_nodes) {
    int e = blockIdx.x * blockDim.x + threadIdx.x;
    if (e < n_edges) {
        int row = edges[e];
        int col = edges[n_edges + e];
        if ((unsigned)row >= (unsigned)n_nodes || (unsigned)col >= (unsigned)n_nodes)
            return;
        int pos = atomicAdd(&g_cursor[row], 1);
        g_csr[pos] = make_int2(col, __float_as_int(w[e]));
    }
}

// ---------------------------------------------------------------------------
// Aggregation: one warp per output node, no atomics.
// ---------------------------------------------------------------------------
__global__ __launch_bounds__(256) void agg_kernel(float* __restrict__ out, int n_nodes) {
    const int lane = threadIdx.x & 31;
    const int node = (blockIdx.x * blockDim.x + threadIdx.x) >> 5;
    if (node >= n_nodes) return;

    const int s = g_start[node];
    const int e = g_start[node + 1];

    float4 acc = make_float4(0.f, 0.f, 0.f, 0.f);
#pragma unroll 4
    for (int i = s; i < e; i++) {
        const int2 cw = g_csr[i];                 // warp-uniform broadcast
        const float wt = __int_as_float(cw.y);
        const float4 v = g_h4[(size_t)cw.x * (D / 4) + lane];
        acc.x += wt * v.x;
        acc.y += wt * v.y;
        acc.z += wt * v.z;
        acc.w += wt * v.w;
    }
    ((float4*)(out + (size_t)node * D))[lane] = acc;
}

// ---------------------------------------------------------------------------
// Launch
// ---------------------------------------------------------------------------
extern "C" void kernel_launch(void* const* d_in, const int* in_sizes, int n_in,
                              void* d_out, int out_size) {
    const float* node_emb    = (const float*)d_in[0];
    const int*   edges       = (const int*)d_in[1];
    const float* edge_weight = (const float*)d_in[2];
    const float* W           = (const float*)d_in[3];
    float*       out         = (float*)d_out;

    const int n_nodes = in_sizes[0] / D;
    const int n_edges = in_sizes[1] / 2;
    const int n_chunks = (n_nodes + CHUNK - 1) / CHUNK;

    // GEMM: h = node_emb @ W^T
    gemm_kernel<<<(n_nodes + 127) / 128, 256, 0, 0>>>(node_emb, W, n_nodes);

    // CSR build
    zero_count_kernel<<<(n_nodes + 255) / 256, 256, 0, 0>>>(n_nodes);
    hist_kernel<<<(n_edges + 255) / 256, 256, 0, 0>>>(edges, n_edges, n_nodes);
    chunk_reduce_kernel<<<n_chunks, 256, 0, 0>>>(n_nodes);
    chunk_scan_kernel<<<1, MAX_CHUNKS, 0, 0>>>(n_chunks, n_nodes, n_edges);
    chunk_apply_kernel<<<n_chunks, CHUNK, 0, 0>>>(n_nodes);
    fill_kernel<<<(n_edges + 255) / 256, 256, 0, 0>>>(edges, edge_weight, n_edges, n_nodes);

    // Atomic-free aggregation; writes every output row (covers zero-degree nodes)
    const int agg_threads = n_nodes * 32;
    agg_kernel<<<(agg_threads + 255) / 256, 256, 0, 0>>>(out, n_nodes);
}